// round 1
// baseline (speedup 1.0000x reference)
#include <cuda_runtime.h>
#include <cstddef>

#define D_MODEL 512
#define S_LEN   512
#define BATCH   64
#define NHEAD   8
#define DH      64
#define ROWS    (S_LEN * BATCH)          // 32768
#define NELEM   ((size_t)ROWS * D_MODEL) // 16,777,216

// ---------------- scratch (no allocations allowed) ----------------
__device__ float g_xn[NELEM];
__device__ float g_q [NELEM];
__device__ float g_k [NELEM];
__device__ float g_v [NELEM];
__device__ float g_att[NELEM];
__device__ float g_xt[NELEM];
__device__ float g_h1[NELEM];

// ---------------- LayerNorm (optionally fused residual add) ----------------
// one block (128 threads) per row of 512 floats
__global__ void __launch_bounds__(128) ln_kernel(
    const float* __restrict__ x, const float* __restrict__ res,
    const float* __restrict__ gamma, const float* __restrict__ beta,
    float* __restrict__ out)
{
    int row = blockIdx.x;
    int t = threadIdx.x;                       // 0..127, each owns one float4
    const float4* xr = (const float4*)(x + (size_t)row * D_MODEL);
    float4 v = xr[t];
    if (res) {
        const float4* rr = (const float4*)(res + (size_t)row * D_MODEL);
        float4 r = rr[t];
        v.x += r.x; v.y += r.y; v.z += r.z; v.w += r.w;
    }
    float s  = v.x + v.y + v.z + v.w;
    float sq = v.x*v.x + v.y*v.y + v.z*v.z + v.w*v.w;
    #pragma unroll
    for (int o = 16; o > 0; o >>= 1) {
        s  += __shfl_xor_sync(0xffffffffu, s,  o);
        sq += __shfl_xor_sync(0xffffffffu, sq, o);
    }
    __shared__ float ss[4], ssq[4];
    int w = t >> 5;
    if ((t & 31) == 0) { ss[w] = s; ssq[w] = sq; }
    __syncthreads();
    s  = ss[0] + ss[1] + ss[2] + ss[3];
    sq = ssq[0] + ssq[1] + ssq[2] + ssq[3];
    const float invD = 1.0f / D_MODEL;
    float mu   = s * invD;
    float var  = sq * invD - mu * mu;
    float rstd = rsqrtf(var + 1e-5f);
    float4 g = ((const float4*)gamma)[t];
    float4 b = ((const float4*)beta )[t];
    float4 o;
    o.x = (v.x - mu) * rstd * g.x + b.x;
    o.y = (v.y - mu) * rstd * g.y + b.y;
    o.z = (v.z - mu) * rstd * g.z + b.z;
    o.w = (v.w - mu) * rstd * g.w + b.w;
    ((float4*)(out + (size_t)row * D_MODEL))[t] = o;
}

// ---------------- SGEMM: C[m,n] = sum_k A[m,k] * W[n,k] (+bias)(+relu)(+res) ----------------
// MODE 0: plain   MODE 1: bias + relu   MODE 2: bias + residual
template<int MODE>
__global__ void __launch_bounds__(256) gemm_kernel(
    const float* __restrict__ A, const float* __restrict__ W,
    const float* __restrict__ bias, const float* __restrict__ res,
    float* __restrict__ C, int M, int N, int K)
{
    constexpr int BM = 128, BN = 128, BK = 16;
    __shared__ float As[BK][BM + 4];
    __shared__ float Bs[BK][BN + 4];
    int tid = threadIdx.x;
    int m0 = blockIdx.y * BM;
    int n0 = blockIdx.x * BN;
    int ty = tid >> 4, tx = tid & 15;

    float acc[8][8];
    #pragma unroll
    for (int i = 0; i < 8; i++)
        #pragma unroll
        for (int j = 0; j < 8; j++) acc[i][j] = 0.0f;

    int lrow = tid >> 2;        // 0..63
    int lc4  = (tid & 3) * 4;   // 0,4,8,12

    for (int k0 = 0; k0 < K; k0 += BK) {
        #pragma unroll
        for (int i = 0; i < 2; i++) {
            int r = lrow + i * 64;
            float4 va = *(const float4*)(A + (size_t)(m0 + r) * K + k0 + lc4);
            As[lc4+0][r] = va.x; As[lc4+1][r] = va.y; As[lc4+2][r] = va.z; As[lc4+3][r] = va.w;
            float4 vb = *(const float4*)(W + (size_t)(n0 + r) * K + k0 + lc4);
            Bs[lc4+0][r] = vb.x; Bs[lc4+1][r] = vb.y; Bs[lc4+2][r] = vb.z; Bs[lc4+3][r] = vb.w;
        }
        __syncthreads();
        #pragma unroll
        for (int kk = 0; kk < BK; kk++) {
            float ar[8], br[8];
            *(float4*)(ar  ) = *(const float4*)&As[kk][ty*8    ];
            *(float4*)(ar+4) = *(const float4*)&As[kk][ty*8 + 4];
            *(float4*)(br  ) = *(const float4*)&Bs[kk][tx*8    ];
            *(float4*)(br+4) = *(const float4*)&Bs[kk][tx*8 + 4];
            #pragma unroll
            for (int i = 0; i < 8; i++)
                #pragma unroll
                for (int j = 0; j < 8; j++)
                    acc[i][j] += ar[i] * br[j];
        }
        __syncthreads();
    }

    #pragma unroll
    for (int i = 0; i < 8; i++) {
        int m = m0 + ty * 8 + i;
        #pragma unroll
        for (int j = 0; j < 8; j += 4) {
            int n = n0 + tx * 8 + j;
            float4 o;
            o.x = acc[i][j]; o.y = acc[i][j+1]; o.z = acc[i][j+2]; o.w = acc[i][j+3];
            if (MODE >= 1) {
                float4 bb = *(const float4*)(bias + n);
                o.x += bb.x; o.y += bb.y; o.z += bb.z; o.w += bb.w;
            }
            if (MODE == 1) {
                o.x = fmaxf(o.x, 0.f); o.y = fmaxf(o.y, 0.f);
                o.z = fmaxf(o.z, 0.f); o.w = fmaxf(o.w, 0.f);
            }
            if (MODE == 2) {
                float4 rr = *(const float4*)(res + (size_t)m * N + n);
                o.x += rr.x; o.y += rr.y; o.z += rr.z; o.w += rr.w;
            }
            *(float4*)(C + (size_t)m * N + n) = o;
        }
    }
}

// ---------------- attention: flash-style per (b,h), Q-tile 64, K/V tile 32 ----------------
__device__ __forceinline__ float f4c(const float4& v, int j) {
    return j == 0 ? v.x : j == 1 ? v.y : j == 2 ? v.z : v.w;
}

__global__ void __launch_bounds__(256) attn_kernel(
    const float* __restrict__ q, const float* __restrict__ k,
    const float* __restrict__ v, float* __restrict__ o)
{
    __shared__ float qs[64][68];
    __shared__ float ks[32][68];
    __shared__ float vs[32][68];
    __shared__ float ps[64][36];

    int b  = blockIdx.z, h = blockIdx.y, qt = blockIdx.x;
    int tid = threadIdx.x;
    int ty = tid >> 4, tx = tid & 15;    // 16x16
    const size_t rowstride = (size_t)BATCH * D_MODEL;   // 32768
    const size_t base = (size_t)b * D_MODEL + h * DH;
    const float inv_temp = 0.125f;       // 1/sqrt(D/H) = 1/8

    // load Q tile (64 x 64), pre-scaled
    {
        int lr = tid >> 2;               // 0..63
        int lc = (tid & 3) * 16;         // 0,16,32,48
        const float* src = q + (size_t)(qt * 64 + lr) * rowstride + base + lc;
        #pragma unroll
        for (int j = 0; j < 16; j += 4) {
            float4 t4 = *(const float4*)(src + j);
            qs[lr][lc+j+0] = t4.x * inv_temp;
            qs[lr][lc+j+1] = t4.y * inv_temp;
            qs[lr][lc+j+2] = t4.z * inv_temp;
            qs[lr][lc+j+3] = t4.w * inv_temp;
        }
    }

    float m_i[4], l_i[4], oacc[4][4];
    #pragma unroll
    for (int i = 0; i < 4; i++) {
        m_i[i] = -1e30f; l_i[i] = 0.0f;
        #pragma unroll
        for (int j = 0; j < 4; j++) oacc[i][j] = 0.0f;
    }

    int lr2 = tid >> 3;                  // 0..31
    int lc2 = (tid & 7) * 8;             // 0..56

    for (int tt = 0; tt < 16; tt++) {
        int t0 = tt * 32;
        __syncthreads();                 // protect ks/vs from previous iter's readers
        {
            const float* ksrc = k + (size_t)(t0 + lr2) * rowstride + base + lc2;
            const float* vsrc = v + (size_t)(t0 + lr2) * rowstride + base + lc2;
            float4 a0 = *(const float4*)(ksrc);
            float4 a1 = *(const float4*)(ksrc + 4);
            ks[lr2][lc2+0]=a0.x; ks[lr2][lc2+1]=a0.y; ks[lr2][lc2+2]=a0.z; ks[lr2][lc2+3]=a0.w;
            ks[lr2][lc2+4]=a1.x; ks[lr2][lc2+5]=a1.y; ks[lr2][lc2+6]=a1.z; ks[lr2][lc2+7]=a1.w;
            float4 b0 = *(const float4*)(vsrc);
            float4 b1 = *(const float4*)(vsrc + 4);
            vs[lr2][lc2+0]=b0.x; vs[lr2][lc2+1]=b0.y; vs[lr2][lc2+2]=b0.z; vs[lr2][lc2+3]=b0.w;
            vs[lr2][lc2+4]=b1.x; vs[lr2][lc2+5]=b1.y; vs[lr2][lc2+6]=b1.z; vs[lr2][lc2+7]=b1.w;
        }
        __syncthreads();

        // scores: 4 rows x 2 cols per thread
        float sc[4][2];
        #pragma unroll
        for (int i = 0; i < 4; i++) { sc[i][0] = 0.f; sc[i][1] = 0.f; }
        #pragma unroll
        for (int kk = 0; kk < 64; kk += 4) {
            float4 a[4], bq[2];
            #pragma unroll
            for (int i = 0; i < 4; i++) a[i]  = *(const float4*)&qs[ty*4 + i][kk];
            #pragma unroll
            for (int j = 0; j < 2; j++) bq[j] = *(const float4*)&ks[tx*2 + j][kk];
            #pragma unroll
            for (int i = 0; i < 4; i++)
                #pragma unroll
                for (int j = 0; j < 2; j++)
                    sc[i][j] += a[i].x*bq[j].x + a[i].y*bq[j].y + a[i].z*bq[j].z + a[i].w*bq[j].w;
        }

        // online softmax bookkeeping (row reductions across tx via 16-lane shfl)
        float rsum[4];
        #pragma unroll
        for (int i = 0; i < 4; i++) {
            float tmax = fmaxf(sc[i][0], sc[i][1]);
            #pragma unroll
            for (int off = 8; off > 0; off >>= 1)
                tmax = fmaxf(tmax, __shfl_xor_sync(0xffffffffu, tmax, off));
            float mnew = fmaxf(m_i[i], tmax);
            float alpha = __expf(m_i[i] - mnew);
            m_i[i] = mnew;
            float p0 = __expf(sc[i][0] - mnew);
            float p1 = __expf(sc[i][1] - mnew);
            ps[ty*4 + i][tx*2 + 0] = p0;
            ps[ty*4 + i][tx*2 + 1] = p1;
            float rs = p0 + p1;
            #pragma unroll
            for (int off = 8; off > 0; off >>= 1)
                rs += __shfl_xor_sync(0xffffffffu, rs, off);
            rsum[i] = rs;
            l_i[i] = l_i[i] * alpha + rs;
            #pragma unroll
            for (int j = 0; j < 4; j++) oacc[i][j] *= alpha;
        }
        __syncthreads();                 // ps visible

        // O += P @ V   (cols tx*4..+3 per thread)
        #pragma unroll
        for (int t = 0; t < 32; t += 4) {
            float4 p[4], vv[4];
            #pragma unroll
            for (int i = 0; i < 4; i++) p[i]  = *(const float4*)&ps[ty*4 + i][t];
            #pragma unroll
            for (int u = 0; u < 4; u++) vv[u] = *(const float4*)&vs[t + u][tx*4];
            #pragma unroll
            for (int i = 0; i < 4; i++)
                #pragma unroll
                for (int j = 0; j < 4; j++)
                    oacc[i][j] += p[i].x * f4c(vv[0], j) + p[i].y * f4c(vv[1], j)
                                + p[i].z * f4c(vv[2], j) + p[i].w * f4c(vv[3], j);
        }
    }

    // finalize
    #pragma unroll
    for (int i = 0; i < 4; i++) {
        float inv_l = 1.0f / l_i[i];
        int s = qt * 64 + ty * 4 + i;
        float4 ov;
        ov.x = oacc[i][0] * inv_l; ov.y = oacc[i][1] * inv_l;
        ov.z = oacc[i][2] * inv_l; ov.w = oacc[i][3] * inv_l;
        *(float4*)(o + (size_t)s * rowstride + base + tx * 4) = ov;
    }
}

// ---------------- launch ----------------
extern "C" void kernel_launch(void* const* d_in, const int* in_sizes, int n_in,
                              void* d_out, int out_size)
{
    const float* x   = (const float*)d_in[0];
    const float* Wq  = (const float*)d_in[1];
    const float* Wk  = (const float*)d_in[2];
    const float* Wv  = (const float*)d_in[3];
    const float* g1  = (const float*)d_in[4];
    const float* b1  = (const float*)d_in[5];
    const float* g2  = (const float*)d_in[6];
    const float* b2  = (const float*)d_in[7];
    const float* W1  = (const float*)d_in[8];
    const float* bf1 = (const float*)d_in[9];
    const float* W2  = (const float*)d_in[10];
    const float* bf2 = (const float*)d_in[11];
    float* out = (float*)d_out;

    float *xn, *qb, *kb, *vb, *att, *xt, *h1;
    cudaGetSymbolAddress((void**)&xn,  g_xn);
    cudaGetSymbolAddress((void**)&qb,  g_q);
    cudaGetSymbolAddress((void**)&kb,  g_k);
    cudaGetSymbolAddress((void**)&vb,  g_v);
    cudaGetSymbolAddress((void**)&att, g_att);
    cudaGetSymbolAddress((void**)&xt,  g_xt);
    cudaGetSymbolAddress((void**)&h1,  g_h1);

    dim3 gg(D_MODEL / 128, ROWS / 128);   // (4, 256)

    ln_kernel<<<ROWS, 128>>>(x, nullptr, g1, b1, xn);
    gemm_kernel<0><<<gg, 256>>>(xn, Wq, nullptr, nullptr, qb, ROWS, D_MODEL, D_MODEL);
    gemm_kernel<0><<<gg, 256>>>(xn, Wk, nullptr, nullptr, kb, ROWS, D_MODEL, D_MODEL);
    gemm_kernel<0><<<gg, 256>>>(xn, Wv, nullptr, nullptr, vb, ROWS, D_MODEL, D_MODEL);
    attn_kernel<<<dim3(S_LEN / 64, NHEAD, BATCH), 256>>>(qb, kb, vb, att);
    ln_kernel<<<ROWS, 128>>>(xn, att, g2, b2, xt);
    gemm_kernel<1><<<gg, 256>>>(xt, W1, bf1, nullptr, h1, ROWS, D_MODEL, D_MODEL);
    gemm_kernel<2><<<gg, 256>>>(h1, W2, bf2, xt, out, ROWS, D_MODEL, D_MODEL);
}

// round 5
// speedup vs baseline: 1.5530x; 1.5530x over previous
#include <cuda_runtime.h>
#include <cuda_bf16.h>
#include <cstdint>
#include <cstddef>

#define D_MODEL 512
#define S_LEN   512
#define BATCH   64
#define NHEAD   8
#define DH      64
#define ROWS    (S_LEN * BATCH)          // 32768
#define NELEM   ((size_t)ROWS * D_MODEL) // 16,777,216

// ---------------- scratch (no allocations allowed) ----------------
__device__ float g_xn[NELEM];
__device__ float g_q [NELEM];
__device__ float g_k [NELEM];
__device__ float g_v [NELEM];
__device__ float g_att[NELEM];
__device__ float g_xt[NELEM];
__device__ float g_h1[NELEM];

// ================= tf32 warp-mma helpers =================
__device__ __forceinline__ uint32_t f2tf32(float f) {
    uint32_t u;
    asm("cvt.rna.tf32.f32 %0, %1;" : "=r"(u) : "f"(f));
    return u;
}
__device__ __forceinline__ void mma_tf32(float* c, const uint32_t* a, uint32_t b0, uint32_t b1) {
    asm volatile(
        "mma.sync.aligned.m16n8k8.row.col.f32.tf32.tf32.f32 "
        "{%0,%1,%2,%3}, {%4,%5,%6,%7}, {%8,%9}, {%0,%1,%2,%3};"
        : "+f"(c[0]), "+f"(c[1]), "+f"(c[2]), "+f"(c[3])
        : "r"(a[0]), "r"(a[1]), "r"(a[2]), "r"(a[3]), "r"(b0), "r"(b1));
}

// ---------------- LayerNorm (optionally fused residual add) ----------------
__global__ void __launch_bounds__(128) ln_kernel(
    const float* __restrict__ x, const float* __restrict__ res,
    const float* __restrict__ gamma, const float* __restrict__ beta,
    float* __restrict__ out)
{
    int row = blockIdx.x;
    int t = threadIdx.x;
    const float4* xr = (const float4*)(x + (size_t)row * D_MODEL);
    float4 v = xr[t];
    if (res) {
        const float4* rr = (const float4*)(res + (size_t)row * D_MODEL);
        float4 r = rr[t];
        v.x += r.x; v.y += r.y; v.z += r.z; v.w += r.w;
    }
    float s  = v.x + v.y + v.z + v.w;
    float sq = v.x*v.x + v.y*v.y + v.z*v.z + v.w*v.w;
    #pragma unroll
    for (int o = 16; o > 0; o >>= 1) {
        s  += __shfl_xor_sync(0xffffffffu, s,  o);
        sq += __shfl_xor_sync(0xffffffffu, sq, o);
    }
    __shared__ float ss[4], ssq[4];
    int w = t >> 5;
    if ((t & 31) == 0) { ss[w] = s; ssq[w] = sq; }
    __syncthreads();
    s  = ss[0] + ss[1] + ss[2] + ss[3];
    sq = ssq[0] + ssq[1] + ssq[2] + ssq[3];
    const float invD = 1.0f / D_MODEL;
    float mu   = s * invD;
    float var  = sq * invD - mu * mu;
    float rstd = rsqrtf(var + 1e-5f);
    float4 g = ((const float4*)gamma)[t];
    float4 b = ((const float4*)beta )[t];
    float4 o;
    o.x = (v.x - mu) * rstd * g.x + b.x;
    o.y = (v.y - mu) * rstd * g.y + b.y;
    o.z = (v.z - mu) * rstd * g.z + b.z;
    o.w = (v.w - mu) * rstd * g.w + b.w;
    ((float4*)(out + (size_t)row * D_MODEL))[t] = o;
}

// ============ tf32 tensor-core GEMM: C[m,n] = sum_k A[m,k]*W[n,k] (+bias)(+relu)(+res) ============
// MODE 0: plain   MODE 1: bias + relu   MODE 2: bias + residual
// CTA tile 128x128, BK=32, 8 warps each 32(M) x 64(N) = 2x8 atoms of m16n8k8.
template<int MODE>
__global__ void __launch_bounds__(256, 2) tc_gemm(
    const float* __restrict__ A, const float* __restrict__ W,
    const float* __restrict__ bias, const float* __restrict__ res,
    float* __restrict__ C)
{
    constexpr int K = 512, N = 512, BK = 32, LDS = 36;  // 36 mod 32 = 4 -> conflict-free frags
    __shared__ uint32_t sA[128 * LDS];   // 18 KB
    __shared__ uint32_t sB[128 * LDS];   // 18 KB

    int tid  = threadIdx.x;
    int wid  = tid >> 5, lane = tid & 31;
    int grp  = lane >> 2, tig = lane & 3;
    int m0 = blockIdx.y * 128, n0 = blockIdx.x * 128;
    int wm = wid & 3;        // warp M offset: wm*32
    int wn = wid >> 2;       // warp N offset: wn*64

    float acc[2][8][4];
    #pragma unroll
    for (int i = 0; i < 2; i++)
        #pragma unroll
        for (int j = 0; j < 8; j++)
            #pragma unroll
            for (int q = 0; q < 4; q++) acc[i][j][q] = 0.0f;

    for (int chunk = 0; chunk < 16; chunk++) {
        int k0 = chunk * BK;
        __syncthreads();   // previous chunk fully consumed
        #pragma unroll
        for (int it = 0; it < 4; it++) {
            int slot = tid + it * 256;        // 1024 float4-slots per operand
            int r  = slot >> 3;               // 0..127
            int c4 = (slot & 7) * 4;          // 0..28
            {
                float4 f = *(const float4*)(A + (size_t)(m0 + r) * K + k0 + c4);
                uint4 u = { f2tf32(f.x), f2tf32(f.y), f2tf32(f.z), f2tf32(f.w) };
                *(uint4*)(sA + r * LDS + c4) = u;
            }
            {
                float4 f = *(const float4*)(W + (size_t)(n0 + r) * K + k0 + c4);
                uint4 u = { f2tf32(f.x), f2tf32(f.y), f2tf32(f.z), f2tf32(f.w) };
                *(uint4*)(sB + r * LDS + c4) = u;
            }
        }
        __syncthreads();

        #pragma unroll
        for (int ks = 0; ks < 4; ks++) {
            int kk = ks * 8;
            uint32_t a[2][4];
            #pragma unroll
            for (int mi = 0; mi < 2; mi++) {
                int r = wm * 32 + mi * 16 + grp;
                a[mi][0] = sA[(r    ) * LDS + kk + tig    ];
                a[mi][1] = sA[(r + 8) * LDS + kk + tig    ];
                a[mi][2] = sA[(r    ) * LDS + kk + tig + 4];
                a[mi][3] = sA[(r + 8) * LDS + kk + tig + 4];
            }
            uint32_t b[8][2];
            #pragma unroll
            for (int ni = 0; ni < 8; ni++) {
                int n = wn * 64 + ni * 8 + grp;
                b[ni][0] = sB[n * LDS + kk + tig    ];
                b[ni][1] = sB[n * LDS + kk + tig + 4];
            }
            #pragma unroll
            for (int mi = 0; mi < 2; mi++)
                #pragma unroll
                for (int ni = 0; ni < 8; ni++)
                    mma_tf32(acc[mi][ni], a[mi], b[ni][0], b[ni][1]);
        }
    }

    // epilogue
    #pragma unroll
    for (int mi = 0; mi < 2; mi++) {
        #pragma unroll
        for (int h = 0; h < 2; h++) {
            int m = m0 + wm * 32 + mi * 16 + grp + h * 8;
            #pragma unroll
            for (int ni = 0; ni < 8; ni++) {
                int n = n0 + wn * 64 + ni * 8 + tig * 2;
                float2 o;
                o.x = acc[mi][ni][h * 2 + 0];
                o.y = acc[mi][ni][h * 2 + 1];
                if (MODE >= 1) {
                    float2 bb = *(const float2*)(bias + n);
                    o.x += bb.x; o.y += bb.y;
                }
                if (MODE == 1) {
                    o.x = fmaxf(o.x, 0.f); o.y = fmaxf(o.y, 0.f);
                }
                if (MODE == 2) {
                    float2 rr = *(const float2*)(res + (size_t)m * N + n);
                    o.x += rr.x; o.y += rr.y;
                }
                *(float2*)(C + (size_t)m * N + n) = o;
            }
        }
    }
}

// ---------------- attention: flash-style per (b,h), Q-tile 64, K/V tile 32 ----------------
__device__ __forceinline__ float f4c(const float4& v, int j) {
    return j == 0 ? v.x : j == 1 ? v.y : j == 2 ? v.z : v.w;
}

__global__ void __launch_bounds__(256) attn_kernel(
    const float* __restrict__ q, const float* __restrict__ k,
    const float* __restrict__ v, float* __restrict__ o)
{
    __shared__ float qs[64][68];
    __shared__ float ks[32][68];
    __shared__ float vs[32][68];
    __shared__ float ps[64][36];

    int b  = blockIdx.z, h = blockIdx.y, qt = blockIdx.x;
    int tid = threadIdx.x;
    int ty = tid >> 4, tx = tid & 15;
    const size_t rowstride = (size_t)BATCH * D_MODEL;
    const size_t base = (size_t)b * D_MODEL + h * DH;
    const float inv_temp = 0.125f;

    {
        int lr = tid >> 2;
        int lc = (tid & 3) * 16;
        const float* src = q + (size_t)(qt * 64 + lr) * rowstride + base + lc;
        #pragma unroll
        for (int j = 0; j < 16; j += 4) {
            float4 t4 = *(const float4*)(src + j);
            qs[lr][lc+j+0] = t4.x * inv_temp;
            qs[lr][lc+j+1] = t4.y * inv_temp;
            qs[lr][lc+j+2] = t4.z * inv_temp;
            qs[lr][lc+j+3] = t4.w * inv_temp;
        }
    }

    float m_i[4], l_i[4], oacc[4][4];
    #pragma unroll
    for (int i = 0; i < 4; i++) {
        m_i[i] = -1e30f; l_i[i] = 0.0f;
        #pragma unroll
        for (int j = 0; j < 4; j++) oacc[i][j] = 0.0f;
    }

    int lr2 = tid >> 3;
    int lc2 = (tid & 7) * 8;

    for (int tt = 0; tt < 16; tt++) {
        int t0 = tt * 32;
        __syncthreads();
        {
            const float* ksrc = k + (size_t)(t0 + lr2) * rowstride + base + lc2;
            const float* vsrc = v + (size_t)(t0 + lr2) * rowstride + base + lc2;
            float4 a0 = *(const float4*)(ksrc);
            float4 a1 = *(const float4*)(ksrc + 4);
            ks[lr2][lc2+0]=a0.x; ks[lr2][lc2+1]=a0.y; ks[lr2][lc2+2]=a0.z; ks[lr2][lc2+3]=a0.w;
            ks[lr2][lc2+4]=a1.x; ks[lr2][lc2+5]=a1.y; ks[lr2][lc2+6]=a1.z; ks[lr2][lc2+7]=a1.w;
            float4 b0 = *(const float4*)(vsrc);
            float4 b1 = *(const float4*)(vsrc + 4);
            vs[lr2][lc2+0]=b0.x; vs[lr2][lc2+1]=b0.y; vs[lr2][lc2+2]=b0.z; vs[lr2][lc2+3]=b0.w;
            vs[lr2][lc2+4]=b1.x; vs[lr2][lc2+5]=b1.y; vs[lr2][lc2+6]=b1.z; vs[lr2][lc2+7]=b1.w;
        }
        __syncthreads();

        float sc[4][2];
        #pragma unroll
        for (int i = 0; i < 4; i++) { sc[i][0] = 0.f; sc[i][1] = 0.f; }
        #pragma unroll
        for (int kk = 0; kk < 64; kk += 4) {
            float4 a[4], bq[2];
            #pragma unroll
            for (int i = 0; i < 4; i++) a[i]  = *(const float4*)&qs[ty*4 + i][kk];
            #pragma unroll
            for (int j = 0; j < 2; j++) bq[j] = *(const float4*)&ks[tx*2 + j][kk];
            #pragma unroll
            for (int i = 0; i < 4; i++)
                #pragma unroll
                for (int j = 0; j < 2; j++)
                    sc[i][j] += a[i].x*bq[j].x + a[i].y*bq[j].y + a[i].z*bq[j].z + a[i].w*bq[j].w;
        }

        #pragma unroll
        for (int i = 0; i < 4; i++) {
            float tmax = fmaxf(sc[i][0], sc[i][1]);
            #pragma unroll
            for (int off = 8; off > 0; off >>= 1)
                tmax = fmaxf(tmax, __shfl_xor_sync(0xffffffffu, tmax, off));
            float mnew = fmaxf(m_i[i], tmax);
            float alpha = __expf(m_i[i] - mnew);
            m_i[i] = mnew;
            float p0 = __expf(sc[i][0] - mnew);
            float p1 = __expf(sc[i][1] - mnew);
            ps[ty*4 + i][tx*2 + 0] = p0;
            ps[ty*4 + i][tx*2 + 1] = p1;
            float rs = p0 + p1;
            #pragma unroll
            for (int off = 8; off > 0; off >>= 1)
                rs += __shfl_xor_sync(0xffffffffu, rs, off);
            l_i[i] = l_i[i] * alpha + rs;
            #pragma unroll
            for (int j = 0; j < 4; j++) oacc[i][j] *= alpha;
        }
        __syncthreads();

        #pragma unroll
        for (int t = 0; t < 32; t += 4) {
            float4 p[4], vv[4];
            #pragma unroll
            for (int i = 0; i < 4; i++) p[i]  = *(const float4*)&ps[ty*4 + i][t];
            #pragma unroll
            for (int u = 0; u < 4; u++) vv[u] = *(const float4*)&vs[t + u][tx*4];
            #pragma unroll
            for (int i = 0; i < 4; i++)
                #pragma unroll
                for (int j = 0; j < 4; j++)
                    oacc[i][j] += p[i].x * f4c(vv[0], j) + p[i].y * f4c(vv[1], j)
                                + p[i].z * f4c(vv[2], j) + p[i].w * f4c(vv[3], j);
        }
    }

    #pragma unroll
    for (int i = 0; i < 4; i++) {
        float inv_l = 1.0f / l_i[i];
        int s = qt * 64 + ty * 4 + i;
        float4 ov;
        ov.x = oacc[i][0] * inv_l; ov.y = oacc[i][1] * inv_l;
        ov.z = oacc[i][2] * inv_l; ov.w = oacc[i][3] * inv_l;
        *(float4*)(o + (size_t)s * rowstride + base + tx * 4) = ov;
    }
}

// ---------------- launch ----------------
extern "C" void kernel_launch(void* const* d_in, const int* in_sizes, int n_in,
                              void* d_out, int out_size)
{
    const float* x   = (const float*)d_in[0];
    const float* Wq  = (const float*)d_in[1];
    const float* Wk  = (const float*)d_in[2];
    const float* Wv  = (const float*)d_in[3];
    const float* g1  = (const float*)d_in[4];
    const float* b1  = (const float*)d_in[5];
    const float* g2  = (const float*)d_in[6];
    const float* b2  = (const float*)d_in[7];
    const float* W1  = (const float*)d_in[8];
    const float* bf1 = (const float*)d_in[9];
    const float* W2  = (const float*)d_in[10];
    const float* bf2 = (const float*)d_in[11];
    float* out = (float*)d_out;

    float *xn, *qb, *kb, *vb, *att, *xt, *h1;
    cudaGetSymbolAddress((void**)&xn,  g_xn);
    cudaGetSymbolAddress((void**)&qb,  g_q);
    cudaGetSymbolAddress((void**)&kb,  g_k);
    cudaGetSymbolAddress((void**)&vb,  g_v);
    cudaGetSymbolAddress((void**)&att, g_att);
    cudaGetSymbolAddress((void**)&xt,  g_xt);
    cudaGetSymbolAddress((void**)&h1,  g_h1);

    dim3 gg(D_MODEL / 128, ROWS / 128);   // (4, 256)

    ln_kernel<<<ROWS, 128>>>(x, nullptr, g1, b1, xn);
    tc_gemm<0><<<gg, 256>>>(xn, Wq, nullptr, nullptr, qb);
    tc_gemm<0><<<gg, 256>>>(xn, Wk, nullptr, nullptr, kb);
    tc_gemm<0><<<gg, 256>>>(xn, Wv, nullptr, nullptr, vb);
    attn_kernel<<<dim3(S_LEN / 64, NHEAD, BATCH), 256>>>(qb, kb, vb, att);
    ln_kernel<<<ROWS, 128>>>(xn, att, g2, b2, xt);
    tc_gemm<1><<<gg, 256>>>(xt, W1, bf1, nullptr, h1);
    tc_gemm<2><<<gg, 256>>>(h1, W2, bf2, xt, out);
}

// round 8
// speedup vs baseline: 2.4481x; 1.5764x over previous
#include <cuda_runtime.h>
#include <cuda_bf16.h>
#include <cstdint>
#include <cstddef>

#define D_MODEL 512
#define S_LEN   512
#define BATCH   64
#define NHEAD   8
#define DH      64
#define ROWS    (S_LEN * BATCH)          // 32768
#define NELEM   ((size_t)ROWS * D_MODEL) // 16,777,216

// ---------------- scratch (no allocations allowed) ----------------
__device__ float g_xn[NELEM];
__device__ float g_q [NELEM];
__device__ float g_k [NELEM];
__device__ float g_v [NELEM];
__device__ float g_att[NELEM];
__device__ float g_xt[NELEM];
__device__ float g_h1[NELEM];

// ================= tf32 warp-mma helpers =================
__device__ __forceinline__ uint32_t f2tf32(float f) {
    uint32_t u;
    asm("cvt.rna.tf32.f32 %0, %1;" : "=r"(u) : "f"(f));
    return u;
}
__device__ __forceinline__ void mma_tf32(float* c, const uint32_t* a, uint32_t b0, uint32_t b1) {
    asm volatile(
        "mma.sync.aligned.m16n8k8.row.col.f32.tf32.tf32.f32 "
        "{%0,%1,%2,%3}, {%4,%5,%6,%7}, {%8,%9}, {%0,%1,%2,%3};"
        : "+f"(c[0]), "+f"(c[1]), "+f"(c[2]), "+f"(c[3])
        : "r"(a[0]), "r"(a[1]), "r"(a[2]), "r"(a[3]), "r"(b0), "r"(b1));
}

// ---------------- LayerNorm (optionally fused residual add) ----------------
__global__ void __launch_bounds__(128) ln_kernel(
    const float* __restrict__ x, const float* __restrict__ res,
    const float* __restrict__ gamma, const float* __restrict__ beta,
    float* __restrict__ out)
{
    int row = blockIdx.x;
    int t = threadIdx.x;
    const float4* xr = (const float4*)(x + (size_t)row * D_MODEL);
    float4 v = xr[t];
    if (res) {
        const float4* rr = (const float4*)(res + (size_t)row * D_MODEL);
        float4 r = rr[t];
        v.x += r.x; v.y += r.y; v.z += r.z; v.w += r.w;
    }
    float s  = v.x + v.y + v.z + v.w;
    float sq = v.x*v.x + v.y*v.y + v.z*v.z + v.w*v.w;
    #pragma unroll
    for (int o = 16; o > 0; o >>= 1) {
        s  += __shfl_xor_sync(0xffffffffu, s,  o);
        sq += __shfl_xor_sync(0xffffffffu, sq, o);
    }
    __shared__ float ss[4], ssq[4];
    int w = t >> 5;
    if ((t & 31) == 0) { ss[w] = s; ssq[w] = sq; }
    __syncthreads();
    s  = ss[0] + ss[1] + ss[2] + ss[3];
    sq = ssq[0] + ssq[1] + ssq[2] + ssq[3];
    const float invD = 1.0f / D_MODEL;
    float mu   = s * invD;
    float var  = sq * invD - mu * mu;
    float rstd = rsqrtf(var + 1e-5f);
    float4 g = ((const float4*)gamma)[t];
    float4 b = ((const float4*)beta )[t];
    float4 o;
    o.x = (v.x - mu) * rstd * g.x + b.x;
    o.y = (v.y - mu) * rstd * g.y + b.y;
    o.z = (v.z - mu) * rstd * g.z + b.z;
    o.w = (v.w - mu) * rstd * g.w + b.w;
    ((float4*)(out + (size_t)row * D_MODEL))[t] = o;
}

// ============ tf32 tensor-core GEMM: C[m,n] = sum_k A[m,k]*W[n,k] (+bias)(+relu)(+res) ============
template<int MODE>
__global__ void __launch_bounds__(256, 2) tc_gemm(
    const float* __restrict__ A, const float* __restrict__ W,
    const float* __restrict__ bias, const float* __restrict__ res,
    float* __restrict__ C)
{
    constexpr int K = 512, N = 512, BK = 32, LDS = 36;
    __shared__ uint32_t sA[128 * LDS];
    __shared__ uint32_t sB[128 * LDS];

    int tid  = threadIdx.x;
    int wid  = tid >> 5, lane = tid & 31;
    int grp  = lane >> 2, tig = lane & 3;
    int m0 = blockIdx.y * 128, n0 = blockIdx.x * 128;
    int wm = wid & 3;
    int wn = wid >> 2;

    float acc[2][8][4];
    #pragma unroll
    for (int i = 0; i < 2; i++)
        #pragma unroll
        for (int j = 0; j < 8; j++)
            #pragma unroll
            for (int q = 0; q < 4; q++) acc[i][j][q] = 0.0f;

    for (int chunk = 0; chunk < 16; chunk++) {
        int k0 = chunk * BK;
        __syncthreads();
        #pragma unroll
        for (int it = 0; it < 4; it++) {
            int slot = tid + it * 256;
            int r  = slot >> 3;
            int c4 = (slot & 7) * 4;
            {
                float4 f = *(const float4*)(A + (size_t)(m0 + r) * K + k0 + c4);
                uint4 u = { f2tf32(f.x), f2tf32(f.y), f2tf32(f.z), f2tf32(f.w) };
                *(uint4*)(sA + r * LDS + c4) = u;
            }
            {
                float4 f = *(const float4*)(W + (size_t)(n0 + r) * K + k0 + c4);
                uint4 u = { f2tf32(f.x), f2tf32(f.y), f2tf32(f.z), f2tf32(f.w) };
                *(uint4*)(sB + r * LDS + c4) = u;
            }
        }
        __syncthreads();

        #pragma unroll
        for (int ks = 0; ks < 4; ks++) {
            int kk = ks * 8;
            uint32_t a[2][4];
            #pragma unroll
            for (int mi = 0; mi < 2; mi++) {
                int r = wm * 32 + mi * 16 + grp;
                a[mi][0] = sA[(r    ) * LDS + kk + tig    ];
                a[mi][1] = sA[(r + 8) * LDS + kk + tig    ];
                a[mi][2] = sA[(r    ) * LDS + kk + tig + 4];
                a[mi][3] = sA[(r + 8) * LDS + kk + tig + 4];
            }
            uint32_t b[8][2];
            #pragma unroll
            for (int ni = 0; ni < 8; ni++) {
                int n = wn * 64 + ni * 8 + grp;
                b[ni][0] = sB[n * LDS + kk + tig    ];
                b[ni][1] = sB[n * LDS + kk + tig + 4];
            }
            #pragma unroll
            for (int mi = 0; mi < 2; mi++)
                #pragma unroll
                for (int ni = 0; ni < 8; ni++)
                    mma_tf32(acc[mi][ni], a[mi], b[ni][0], b[ni][1]);
        }
    }

    #pragma unroll
    for (int mi = 0; mi < 2; mi++) {
        #pragma unroll
        for (int h = 0; h < 2; h++) {
            int m = m0 + wm * 32 + mi * 16 + grp + h * 8;
            #pragma unroll
            for (int ni = 0; ni < 8; ni++) {
                int n = n0 + wn * 64 + ni * 8 + tig * 2;
                float2 o;
                o.x = acc[mi][ni][h * 2 + 0];
                o.y = acc[mi][ni][h * 2 + 1];
                if (MODE >= 1) {
                    float2 bb = *(const float2*)(bias + n);
                    o.x += bb.x; o.y += bb.y;
                }
                if (MODE == 1) {
                    o.x = fmaxf(o.x, 0.f); o.y = fmaxf(o.y, 0.f);
                }
                if (MODE == 2) {
                    float2 rr = *(const float2*)(res + (size_t)m * N + n);
                    o.x += rr.x; o.y += rr.y;
                }
                *(float2*)(C + (size_t)m * N + n) = o;
            }
        }
    }
}

// ============ tf32 tensor-core flash attention ============
// Per CTA: (b, h, qtile). Q tile 64 rows; K/V tiles of 64 tokens, 8 tiles.
// 8 warps in 4(row) x 2(col) grid; warp tile 16 x 32.
__global__ void __launch_bounds__(256, 2) attn_tc_kernel(
    const float* __restrict__ q, const float* __restrict__ k,
    const float* __restrict__ v, float* __restrict__ o)
{
    constexpr int LDS = 68;   // 68 mod 32 = 4 -> 4*grp+tig unique -> conflict-free frags
    __shared__ uint32_t ks_ps[64 * LDS];   // K tile, then aliased as P tile
    __shared__ uint32_t vsT [64 * LDS];    // V tile transposed [dh][token]
    __shared__ float pmax[2][64];
    __shared__ float psum[2][64];

    int b = blockIdx.z, h = blockIdx.y, qt = blockIdx.x;
    int tid  = threadIdx.x;
    int wid  = tid >> 5, lane = tid & 31;
    int grp  = lane >> 2, tig = lane & 3;
    int wr = wid & 3;    // rows wr*16
    int wc = wid >> 2;   // cols wc*32
    const size_t rowstride = (size_t)BATCH * D_MODEL;
    const size_t base = (size_t)b * D_MODEL + h * DH;

    // Q fragments, pre-scaled by 1/temperature = 0.125
    uint32_t qf[8][4];
    {
        const float* q0 = q + (size_t)(qt * 64 + wr * 16 + grp) * rowstride + base;
        const float* q1 = q0 + 8 * rowstride;
        #pragma unroll
        for (int s = 0; s < 8; s++) {
            qf[s][0] = f2tf32(q0[s * 8 + tig    ] * 0.125f);
            qf[s][1] = f2tf32(q1[s * 8 + tig    ] * 0.125f);
            qf[s][2] = f2tf32(q0[s * 8 + tig + 4] * 0.125f);
            qf[s][3] = f2tf32(q1[s * 8 + tig + 4] * 0.125f);
        }
    }

    float m0 = -1e30f, m1 = -1e30f, l0 = 0.0f, l1 = 0.0f;
    float oacc[4][4];
    #pragma unroll
    for (int i = 0; i < 4; i++)
        #pragma unroll
        for (int j = 0; j < 4; j++) oacc[i][j] = 0.0f;

    int lr = tid >> 2;            // 0..63
    int lc = (tid & 3) * 16;      // 0,16,32,48
    int row0 = wr * 16 + grp, row1 = row0 + 8;

    for (int tt = 0; tt < 8; tt++) {
        int t0 = tt * 64;
        __syncthreads();   // prior GEMM2 reads of ks_ps/vsT done
        {
            const float* ksrc = k + (size_t)(t0 + lr) * rowstride + base + lc;
            const float* vsrc = v + (size_t)(t0 + lr) * rowstride + base + lc;
            #pragma unroll
            for (int j = 0; j < 16; j += 4) {
                float4 f = *(const float4*)(ksrc + j);
                uint4 u = { f2tf32(f.x), f2tf32(f.y), f2tf32(f.z), f2tf32(f.w) };
                *(uint4*)(ks_ps + lr * LDS + lc + j) = u;
                float4 g = *(const float4*)(vsrc + j);
                vsT[(lc + j + 0) * LDS + lr] = f2tf32(g.x);
                vsT[(lc + j + 1) * LDS + lr] = f2tf32(g.y);
                vsT[(lc + j + 2) * LDS + lr] = f2tf32(g.z);
                vsT[(lc + j + 3) * LDS + lr] = f2tf32(g.w);
            }
        }
        __syncthreads();

        // GEMM1: S tile (rows wr*16.., cols wc*32..)
        float sc[4][4];
        #pragma unroll
        for (int i = 0; i < 4; i++)
            #pragma unroll
            for (int j = 0; j < 4; j++) sc[i][j] = 0.0f;
        #pragma unroll
        for (int s = 0; s < 8; s++) {
            int kk = s * 8;
            #pragma unroll
            for (int ni = 0; ni < 4; ni++) {
                int n = wc * 32 + ni * 8 + grp;
                uint32_t b0 = ks_ps[n * LDS + kk + tig    ];
                uint32_t b1 = ks_ps[n * LDS + kk + tig + 4];
                mma_tf32(sc[ni], qf[s], b0, b1);
            }
        }

        // partial row max over this warp's 32 cols
        float t0m = -1e30f, t1m = -1e30f;
        #pragma unroll
        for (int ni = 0; ni < 4; ni++) {
            t0m = fmaxf(t0m, fmaxf(sc[ni][0], sc[ni][1]));
            t1m = fmaxf(t1m, fmaxf(sc[ni][2], sc[ni][3]));
        }
        t0m = fmaxf(t0m, __shfl_xor_sync(0xffffffffu, t0m, 1));
        t0m = fmaxf(t0m, __shfl_xor_sync(0xffffffffu, t0m, 2));
        t1m = fmaxf(t1m, __shfl_xor_sync(0xffffffffu, t1m, 1));
        t1m = fmaxf(t1m, __shfl_xor_sync(0xffffffffu, t1m, 2));
        if (tig == 0) { pmax[wc][row0] = t0m; pmax[wc][row1] = t1m; }
        __syncthreads();   // also: all warps done reading ks -> safe to alias as P

        float fm0 = fmaxf(pmax[0][row0], pmax[1][row0]);
        float fm1 = fmaxf(pmax[0][row1], pmax[1][row1]);
        float mn0 = fmaxf(m0, fm0), mn1 = fmaxf(m1, fm1);
        float al0 = __expf(m0 - mn0), al1 = __expf(m1 - mn1);
        m0 = mn0; m1 = mn1;

        float rs0 = 0.0f, rs1 = 0.0f;
        #pragma unroll
        for (int ni = 0; ni < 4; ni++) {
            float p00 = __expf(sc[ni][0] - mn0);
            float p01 = __expf(sc[ni][1] - mn0);
            float p10 = __expf(sc[ni][2] - mn1);
            float p11 = __expf(sc[ni][3] - mn1);
            rs0 += p00 + p01; rs1 += p10 + p11;
            int col = wc * 32 + ni * 8 + tig * 2;
            uint2 u0 = { f2tf32(p00), f2tf32(p01) };
            uint2 u1 = { f2tf32(p10), f2tf32(p11) };
            *(uint2*)(ks_ps + row0 * LDS + col) = u0;
            *(uint2*)(ks_ps + row1 * LDS + col) = u1;
        }
        rs0 += __shfl_xor_sync(0xffffffffu, rs0, 1);
        rs0 += __shfl_xor_sync(0xffffffffu, rs0, 2);
        rs1 += __shfl_xor_sync(0xffffffffu, rs1, 1);
        rs1 += __shfl_xor_sync(0xffffffffu, rs1, 2);
        if (tig == 0) { psum[wc][row0] = rs0; psum[wc][row1] = rs1; }
        __syncthreads();   // P + psum visible

        l0 = l0 * al0 + psum[0][row0] + psum[1][row0];
        l1 = l1 * al1 + psum[0][row1] + psum[1][row1];
        #pragma unroll
        for (int ni = 0; ni < 4; ni++) {
            oacc[ni][0] *= al0; oacc[ni][1] *= al0;
            oacc[ni][2] *= al1; oacc[ni][3] *= al1;
        }

        // GEMM2: O += P @ V (rows wr*16.., dh cols wc*32..)
        #pragma unroll
        for (int s = 0; s < 8; s++) {
            int kk = s * 8;
            uint32_t a[4];
            a[0] = ks_ps[row0 * LDS + kk + tig    ];
            a[1] = ks_ps[row1 * LDS + kk + tig    ];
            a[2] = ks_ps[row0 * LDS + kk + tig + 4];
            a[3] = ks_ps[row1 * LDS + kk + tig + 4];
            #pragma unroll
            for (int ni = 0; ni < 4; ni++) {
                int n = wc * 32 + ni * 8 + grp;
                uint32_t b0 = vsT[n * LDS + kk + tig    ];
                uint32_t b1 = vsT[n * LDS + kk + tig + 4];
                mma_tf32(oacc[ni], a, b0, b1);
            }
        }
    }

    // finalize
    float il0 = 1.0f / l0, il1 = 1.0f / l1;
    int gr0 = qt * 64 + row0, gr1 = qt * 64 + row1;
    #pragma unroll
    for (int ni = 0; ni < 4; ni++) {
        size_t col = base + wc * 32 + ni * 8 + tig * 2;
        float2 o0 = { oacc[ni][0] * il0, oacc[ni][1] * il0 };
        float2 o1 = { oacc[ni][2] * il1, oacc[ni][3] * il1 };
        *(float2*)(o + (size_t)gr0 * rowstride + col) = o0;
        *(float2*)(o + (size_t)gr1 * rowstride + col) = o1;
    }
}

// ---------------- launch ----------------
extern "C" void kernel_launch(void* const* d_in, const int* in_sizes, int n_in,
                              void* d_out, int out_size)
{
    const float* x   = (const float*)d_in[0];
    const float* Wq  = (const float*)d_in[1];
    const float* Wk  = (const float*)d_in[2];
    const float* Wv  = (const float*)d_in[3];
    const float* g1  = (const float*)d_in[4];
    const float* b1  = (const float*)d_in[5];
    const float* g2  = (const float*)d_in[6];
    const float* b2  = (const float*)d_in[7];
    const float* W1  = (const float*)d_in[8];
    const float* bf1 = (const float*)d_in[9];
    const float* W2  = (const float*)d_in[10];
    const float* bf2 = (const float*)d_in[11];
    float* out = (float*)d_out;

    float *xn, *qb, *kb, *vb, *att, *xt, *h1;
    cudaGetSymbolAddress((void**)&xn,  g_xn);
    cudaGetSymbolAddress((void**)&qb,  g_q);
    cudaGetSymbolAddress((void**)&kb,  g_k);
    cudaGetSymbolAddress((void**)&vb,  g_v);
    cudaGetSymbolAddress((void**)&att, g_att);
    cudaGetSymbolAddress((void**)&xt,  g_xt);
    cudaGetSymbolAddress((void**)&h1,  g_h1);

    dim3 gg(D_MODEL / 128, ROWS / 128);   // (4, 256)

    ln_kernel<<<ROWS, 128>>>(x, nullptr, g1, b1, xn);
    tc_gemm<0><<<gg, 256>>>(xn, Wq, nullptr, nullptr, qb);
    tc_gemm<0><<<gg, 256>>>(xn, Wk, nullptr, nullptr, kb);
    tc_gemm<0><<<gg, 256>>>(xn, Wv, nullptr, nullptr, vb);
    attn_tc_kernel<<<dim3(S_LEN / 64, NHEAD, BATCH), 256>>>(qb, kb, vb, att);
    ln_kernel<<<ROWS, 128>>>(xn, att, g2, b2, xt);
    tc_gemm<1><<<gg, 256>>>(xt, W1, bf1, nullptr, h1);
    tc_gemm<2><<<gg, 256>>>(h1, W2, bf2, xt, out);
}